// round 1
// baseline (speedup 1.0000x reference)
#include <cuda_runtime.h>

// CubicShapeFunction: 500K points, 4^3 cubic B-spline stencil.
// Output layout (concatenated flat float32):
//   [0              , N*64)        shapef_stack  [N,64]
//   [N*64           , N*64 + N*192) shapef_grad  [N,64,3]
//
// Per point, per axis a, offset o in {0..3}:
//   x = rel_a - (floor(rel_a) - 1 + o)  => fixed spline branch per o:
//   o=0: x in [1,2)  (c4),  o=1: [0,1) (c3),  o=2: [-1,0) (c2),  o=3: [-2,-1) (c1)

constexpr int   N_POINTS  = 500000;
constexpr float INV_CELL  = 20.0f;
constexpr int   PTS_PER_BLOCK = 4;      // 500000 % 4 == 0 -> no tail handling
constexpr int   THREADS   = 256;

__global__ __launch_bounds__(THREADS)
void cubic_shape_kernel(const float* __restrict__ pos, float* __restrict__ out) {
    __shared__ float s_b [PTS_PER_BLOCK][3][4];   // basis
    __shared__ float s_db[PTS_PER_BLOCK][3][4];   // d(basis) * INV_CELL
    __shared__ float s_sf[PTS_PER_BLOCK * 64];        // 256 floats staging
    __shared__ float s_gr[PTS_PER_BLOCK * 64 * 3];    // 768 floats staging

    const int tid = threadIdx.x;
    const int pt0 = blockIdx.x * PTS_PER_BLOCK;

    // ---- Phase 1: 48 threads build the spline table (12 entries per point) ----
    if (tid < PTS_PER_BLOCK * 12) {
        const int p    = tid / 12;
        const int r    = tid % 12;
        const int axis = r >> 2;
        const int o    = r & 3;
        const int pt   = pt0 + p;

        const float pp   = pos[pt * 3 + axis];
        const float rel  = pp * INV_CELL;                 // ORIGIN = 0
        const float base = floorf(rel) - 1.0f;
        const float x    = rel - (base + (float)o);       // matches reference expr

        float bb, dd;
        if (o == 0) {            // x in [1,2): c4 branch
            bb = (((-1.0f/6.0f) * x + 1.0f) * x - 2.0f) * x + 4.0f/3.0f;
            dd = (-0.5f * x + 2.0f) * x - 2.0f;
        } else if (o == 1) {     // x in [0,1): c3 branch
            bb = (0.5f * x - 1.0f) * x * x + 2.0f/3.0f;
            dd = (1.5f * x - 2.0f) * x;
        } else if (o == 2) {     // x in [-1,0): c2 branch
            bb = (-0.5f * x - 1.0f) * x * x + 2.0f/3.0f;
            dd = (-1.5f * x - 2.0f) * x;
        } else {                 // x in [-2,-1): c1 branch
            bb = (((1.0f/6.0f) * x + 1.0f) * x + 2.0f) * x + 4.0f/3.0f;
            dd = (0.5f * x + 2.0f) * x + 2.0f;
        }
        s_b [p][axis][o] = bb;
        s_db[p][axis][o] = INV_CELL * dd;
    }
    __syncthreads();

    // ---- Phase 2: each thread computes one (point, stencil-entry) -> 4 floats ----
    {
        const int p = tid >> 6;
        const int s = tid & 63;
        const int i = s >> 4;
        const int j = (s >> 2) & 3;
        const int k = s & 3;

        const float bx  = s_b [p][0][i];
        const float by  = s_b [p][1][j];
        const float bz  = s_b [p][2][k];
        const float dbx = s_db[p][0][i];
        const float dby = s_db[p][1][j];
        const float dbz = s_db[p][2][k];

        const float byz = by * bz;
        s_sf[tid] = bx * byz;

        float* g = &s_gr[tid * 3];     // stride-3 across lanes: conflict-free
        g[0] = dbx * byz;
        g[1] = dby * bx * bz;
        g[2] = dbz * bx * by;
    }
    __syncthreads();

    // ---- Phase 3: drain staging with coalesced 16B streaming stores ----
    const float4* sf4 = (const float4*)s_sf;   // 64 float4
    const float4* gr4 = (const float4*)s_gr;   // 192 float4

    float4* out_sf = (float4*)out + (size_t)pt0 * 16;                        // 16 float4/pt
    float4* out_gr = (float4*)(out + (size_t)N_POINTS * 64) + (size_t)pt0 * 48; // 48 float4/pt

    if (tid < 64) {
        __stcs(&out_sf[tid], sf4[tid]);
    } else {
        __stcs(&out_gr[tid - 64], gr4[tid - 64]);
    }
}

extern "C" void kernel_launch(void* const* d_in, const int* in_sizes, int n_in,
                              void* d_out, int out_size) {
    const float* pos = (const float*)d_in[0];
    float* out = (float*)d_out;
    const int nblocks = N_POINTS / PTS_PER_BLOCK;   // 125000, exact
    cubic_shape_kernel<<<nblocks, THREADS>>>(pos, out);
}